// round 4
// baseline (speedup 1.0000x reference)
#include <cuda_runtime.h>
#include <math.h>

#define DIM   1536
#define HEADS 12
#define HD    128
#define MAXL  4096
#define MAX_ATTN 1920

// ---------------- scratch (no allocations allowed) ----------------
__device__ float g_q [MAXL * DIM];
__device__ float g_k [MAXL * DIM];
__device__ float g_v [MAXL * DIM];
__device__ float g_ao[MAXL * DIM];

// ================= GEMM: C[m,n] = sum_k A[m,k]*B[n,k] + bias[n] =================
#define BM 64
#define BN 64
#define BKK 16

__global__ void __launch_bounds__(256) gemm_nt_bias(
    const float* __restrict__ A, const float* __restrict__ B,
    const float* __restrict__ bias, float* __restrict__ C,
    int M, int N, int K)
{
    __shared__ float As[BKK][BM + 4];
    __shared__ float Bs[BKK][BN + 4];
    const int tid = threadIdx.x;
    const int tx = tid & 15, ty = tid >> 4;
    const int bm = blockIdx.y * BM, bn = blockIdx.x * BN;
    float acc[4][4] = {};
    for (int k0 = 0; k0 < K; k0 += BKK) {
        #pragma unroll
        for (int i = 0; i < 4; i++) {
            int idx = tid + i * 256;          // 0..1023
            int r = idx >> 4, c = idx & 15;   // r: 0..63, c: 0..15
            As[c][r] = A[(size_t)(bm + r) * K + k0 + c];
            Bs[c][r] = B[(size_t)(bn + r) * K + k0 + c];
        }
        __syncthreads();
        #pragma unroll
        for (int kk = 0; kk < BKK; kk++) {
            float4 a4 = *(const float4*)&As[kk][ty * 4];
            float4 b4 = *(const float4*)&Bs[kk][tx * 4];
            float a[4] = {a4.x, a4.y, a4.z, a4.w};
            float b[4] = {b4.x, b4.y, b4.z, b4.w};
            #pragma unroll
            for (int i = 0; i < 4; i++)
                #pragma unroll
                for (int j = 0; j < 4; j++)
                    acc[i][j] += a[i] * b[j];
        }
        __syncthreads();
    }
    #pragma unroll
    for (int i = 0; i < 4; i++) {
        int m = bm + ty * 4 + i;
        #pragma unroll
        for (int j = 0; j < 4; j++) {
            int n = bn + tx * 4 + j;
            C[(size_t)m * N + n] = acc[i][j] + bias[n];
        }
    }
}

// ================= RMSNorm + RoPE (q and k) =================
// One block per (row, which). Row length DIM=1536 -> 768 float2, 256 threads x 3.
__global__ void __launch_bounds__(256) norm_rope_kernel(
    float* __restrict__ qbuf, float* __restrict__ kbuf,
    const float* __restrict__ nqw, const float* __restrict__ nkw,
    const float* __restrict__ freqs, const int* __restrict__ grid_sizes)
{
    const int row = blockIdx.x;
    float* buf = blockIdx.y ? kbuf : qbuf;
    const float* w = blockIdx.y ? nkw : nqw;
    const int tid = threadIdx.x;
    float2* rowp = (float2*)(buf + (size_t)row * DIM);
    const float2* wp = (const float2*)w;

    float2 v[3];
    float ss = 0.f;
    #pragma unroll
    for (int i = 0; i < 3; i++) {
        v[i] = rowp[tid + i * 256];
        ss += v[i].x * v[i].x + v[i].y * v[i].y;
    }
    #pragma unroll
    for (int o = 16; o > 0; o >>= 1) ss += __shfl_xor_sync(0xffffffffu, ss, o);
    __shared__ float red[8];
    if ((tid & 31) == 0) red[tid >> 5] = ss;
    __syncthreads();
    float tot = 0.f;
    #pragma unroll
    for (int i = 0; i < 8; i++) tot += red[i];
    const float rms = rsqrtf(tot * (1.0f / DIM) + 1e-6f);

    const int H = grid_sizes[1], W = grid_sizes[2];
    const int fs = H * W;
    const int fidx = row / fs;
    const int rem = row - fidx * fs;
    const int hh = rem / W;
    const int ww = rem - hh * W;

    #pragma unroll
    for (int i = 0; i < 3; i++) {
        int p = tid + i * 256;               // float2 index within row: 0..767
        float2 wv2 = wp[p];
        float a = v[i].x * rms * wv2.x;
        float b = v[i].y * rms * wv2.y;
        int jj = p & 63;                     // pair index within head (HD/2 = 64)
        int frow = (jj < 22) ? fidx : (jj < 43 ? hh : ww);  // c1=22, c1+c2=43
        float fre = freqs[frow * 128 + jj * 2];
        float fim = freqs[frow * 128 + jj * 2 + 1];
        float2 o;
        o.x = a * fre - b * fim;
        o.y = a * fim + b * fre;
        rowp[p] = o;
    }
}

// ================= Flash attention =================
// Block: 128 threads, 16 queries x 32-key tiles. Mask boundaries (sink=fs, window
// start) are multiples of 32 and uniform across the block's queries (same frame),
// so tiles are either fully allowed or fully skipped.
#define BQ 16
#define TK 32
#define KROW 132     // K tile row stride (floats): conflict-free for row-indexed reads
#define VROW 160     // V tile row stride with 4-float skew per 16-dim group
#define PROW 40      // p tile row stride

__global__ void __launch_bounds__(128) attn_kernel(
    const float* __restrict__ Q, const float* __restrict__ Kb,
    const float* __restrict__ Vb, float* __restrict__ O,
    const int* __restrict__ grid_sizes)
{
    __shared__ float qs[BQ * 128];
    __shared__ float ks[TK * KROW];
    __shared__ float vs[TK * VROW];
    __shared__ float ps[BQ * PROW];

    const int tid = threadIdx.x;
    const int h = blockIdx.y;
    const int q0 = blockIdx.x * BQ;
    const int H = grid_sizes[1], W = grid_sizes[2];
    const int fs = H * W;
    const int f = q0 / fs;
    const int kend = (f + 1) * fs;
    const int sink = fs;                 // SINK_SIZE=1 frame
    const int wstart = kend - MAX_ATTN;  // may be <= sink (then no gap)
    const float scale = rsqrtf((float)HD);

    // load q tile (scale folded in)
    #pragma unroll
    for (int i = 0; i < 4; i++) {
        int idx = tid + i * 128;         // float4 idx over 16*32
        int r = idx >> 5, d4 = idx & 31;
        float4 qv = *(const float4*)&Q[(size_t)(q0 + r) * DIM + h * HD + d4 * 4];
        qv.x *= scale; qv.y *= scale; qv.z *= scale; qv.w *= scale;
        *(float4*)&qs[r * 128 + d4 * 4] = qv;
    }

    const int qi = tid >> 3;            // query owned: 0..15
    const int kg = tid & 7;             // key subgroup / dim group: 0..7
    const int vposbase = kg * 20;       // skewed position: kg*16 + kg*4

    float m_i = -1e30f, l_i = 0.f;
    float o[16];
    #pragma unroll
    for (int i = 0; i < 16; i++) o[i] = 0.f;

    for (int k0 = 0; k0 < kend; k0 += TK) {
        if (k0 >= sink && k0 < wstart) continue;   // uniform across block
        __syncthreads();
        // load K and V tiles (V skewed: d -> d + 4*(d/16))
        #pragma unroll
        for (int i = 0; i < 8; i++) {
            int idx = tid + i * 128;     // float4 idx over 32*32
            int kk = idx >> 5, d4 = idx & 31;
            float4 kv = *(const float4*)&Kb[(size_t)(k0 + kk) * DIM + h * HD + d4 * 4];
            *(float4*)&ks[kk * KROW + d4 * 4] = kv;
            float4 vv = *(const float4*)&Vb[(size_t)(k0 + kk) * DIM + h * HD + d4 * 4];
            int pos = d4 * 4 + (d4 >> 2) * 4;
            *(float4*)&vs[kk * VROW + pos] = vv;
        }
        __syncthreads();

        // scores: this thread handles keys kg + 8j, j=0..3, for query qi
        float s[4] = {0.f, 0.f, 0.f, 0.f};
        {
            const float4* q4 = (const float4*)&qs[qi * 128];
            #pragma unroll
            for (int d4 = 0; d4 < 32; d4++) {
                float4 qv = q4[d4];
                #pragma unroll
                for (int j = 0; j < 4; j++) {
                    float4 kv = *(const float4*)&ks[(kg + 8 * j) * KROW + d4 * 4];
                    s[j] += qv.x * kv.x + qv.y * kv.y + qv.z * kv.z + qv.w * kv.w;
                }
            }
        }
        // online softmax within the 8-lane group
        float mt = fmaxf(fmaxf(s[0], s[1]), fmaxf(s[2], s[3]));
        #pragma unroll
        for (int off = 4; off > 0; off >>= 1)
            mt = fmaxf(mt, __shfl_xor_sync(0xffffffffu, mt, off));
        float m_new = fmaxf(m_i, mt);
        float p[4], psum = 0.f;
        #pragma unroll
        for (int j = 0; j < 4; j++) { p[j] = __expf(s[j] - m_new); psum += p[j]; }
        #pragma unroll
        for (int off = 4; off > 0; off >>= 1)
            psum += __shfl_xor_sync(0xffffffffu, psum, off);
        float corr = __expf(m_i - m_new);
        l_i = l_i * corr + psum;
        m_i = m_new;
        #pragma unroll
        for (int i = 0; i < 16; i++) o[i] *= corr;
        #pragma unroll
        for (int j = 0; j < 4; j++) ps[qi * PROW + kg + 8 * j] = p[j];
        __syncwarp();

        // PV: thread accumulates dims [kg*16, kg*16+16) of query qi
        #pragma unroll 4
        for (int kk = 0; kk < TK; kk++) {
            float pv = ps[qi * PROW + kk];
            const float* vrow = &vs[kk * VROW + vposbase];
            #pragma unroll
            for (int t = 0; t < 4; t++) {
                float4 vv = *(const float4*)(vrow + 4 * t);
                o[4 * t + 0] += pv * vv.x;
                o[4 * t + 1] += pv * vv.y;
                o[4 * t + 2] += pv * vv.z;
                o[4 * t + 3] += pv * vv.w;
            }
        }
    }

    const float inv = 1.0f / l_i;
    const int dbase = kg * 16;
    #pragma unroll
    for (int t = 0; t < 4; t++) {
        float4 ov;
        ov.x = o[4 * t + 0] * inv;
        ov.y = o[4 * t + 1] * inv;
        ov.z = o[4 * t + 2] * inv;
        ov.w = o[4 * t + 3] * inv;
        *(float4*)&O[(size_t)(q0 + qi) * DIM + h * HD + dbase + 4 * t] = ov;
    }
}

// ================= launch =================
extern "C" void kernel_launch(void* const* d_in, const int* in_sizes, int n_in,
                              void* d_out, int out_size)
{
    const float* x          = (const float*)d_in[0];
    const int*   grid_sizes = (const int*)  d_in[2];
    const float* freqs      = (const float*)d_in[3];
    const float* wq = (const float*)d_in[4];
    const float* bq = (const float*)d_in[5];
    const float* wk = (const float*)d_in[6];
    const float* bk = (const float*)d_in[7];
    const float* wv = (const float*)d_in[8];
    const float* bv = (const float*)d_in[9];
    const float* wo = (const float*)d_in[10];
    const float* bo = (const float*)d_in[11];
    const float* nqw = (const float*)d_in[12];
    const float* nkw = (const float*)d_in[13];

    const int L = in_sizes[0] / DIM;

    float *gq, *gk, *gv, *gao;
    cudaGetSymbolAddress((void**)&gq,  g_q);
    cudaGetSymbolAddress((void**)&gk,  g_k);
    cudaGetSymbolAddress((void**)&gv,  g_v);
    cudaGetSymbolAddress((void**)&gao, g_ao);

    dim3 ggrid(DIM / BN, L / BM);
    gemm_nt_bias<<<ggrid, 256>>>(x, wq, bq, gq, L, DIM, DIM);
    gemm_nt_bias<<<ggrid, 256>>>(x, wk, bk, gk, L, DIM, DIM);
    gemm_nt_bias<<<ggrid, 256>>>(x, wv, bv, gv, L, DIM, DIM);

    norm_rope_kernel<<<dim3(L, 2), 256>>>(gq, gk, nqw, nkw, freqs, grid_sizes);

    attn_kernel<<<dim3(L / BQ, HEADS), 128>>>(gq, gk, gv, gao, grid_sizes);

    gemm_nt_bias<<<ggrid, 256>>>(gao, wo, bo, (float*)d_out, L, DIM, DIM);
}

// round 12
// speedup vs baseline: 1.2339x; 1.2339x over previous
#include <cuda_runtime.h>
#include <cuda_bf16.h>
#include <mma.h>
#include <math.h>

#define DIM   1536
#define HEADS 12
#define HD    128
#define MAXL  4096
#define MAX_ATTN 1920

using namespace nvcuda;

// ---------------- scratch (no allocations allowed) ----------------
__device__ float g_q [MAXL * DIM];
__device__ float g_k [MAXL * DIM];
__device__ float g_v [MAXL * DIM];
__device__ float g_ao[MAXL * DIM];
__device__ __nv_bfloat16 g_x_hi [MAXL * DIM];
__device__ __nv_bfloat16 g_x_lo [MAXL * DIM];
__device__ __nv_bfloat16 g_ao_hi[MAXL * DIM];
__device__ __nv_bfloat16 g_ao_lo[MAXL * DIM];
__device__ __nv_bfloat16 g_w_hi [4 * DIM * DIM];
__device__ __nv_bfloat16 g_w_lo [4 * DIM * DIM];

// ================= fp32 -> bf16 hi/lo split =================
__global__ void __launch_bounds__(256) f2bf_split_kernel(
    const float* __restrict__ in,
    __nv_bfloat16* __restrict__ hi, __nv_bfloat16* __restrict__ lo, int n4)
{
    int i = blockIdx.x * blockDim.x + threadIdx.x;
    if (i < n4) {
        float4 v = ((const float4*)in)[i];
        float vv[4];
        vv[0] = v.x; vv[1] = v.y; vv[2] = v.z; vv[3] = v.w;
        __nv_bfloat16 h[4];
        __nv_bfloat16 l[4];
        for (int j = 0; j < 4; j++) {
            h[j] = __float2bfloat16(vv[j]);
            l[j] = __float2bfloat16(vv[j] - __bfloat162float(h[j]));
        }
        __nv_bfloat162 h0; h0.x = h[0]; h0.y = h[1];
        __nv_bfloat162 h1; h1.x = h[2]; h1.y = h[3];
        __nv_bfloat162 l0; l0.x = l[0]; l0.y = l[1];
        __nv_bfloat162 l1; l1.x = l[2]; l1.y = l[3];
        ((__nv_bfloat162*)hi)[2 * i]     = h0;
        ((__nv_bfloat162*)hi)[2 * i + 1] = h1;
        ((__nv_bfloat162*)lo)[2 * i]     = l0;
        ((__nv_bfloat162*)lo)[2 * i + 1] = l1;
    }
}

// ================= split-bf16 WMMA tensor-core GEMM =================
// C = Ahi*Bhi^T + Ahi*Blo^T + Alo*Bhi^T + bias  (fp32 accumulate)
// Block tile 128x128, K-chunk 32, 8 warps (2m x 4n), warp tile 64x32.
#define GBM 128
#define GBN 128
#define GBK 32
#define LDT 40   // smem row stride in bf16 elems

__global__ void __launch_bounds__(256) gemm_bf16x3_nt(
    const __nv_bfloat16* __restrict__ Ahi, const __nv_bfloat16* __restrict__ Alo,
    const __nv_bfloat16* __restrict__ Bhi, const __nv_bfloat16* __restrict__ Blo,
    const float* __restrict__ bias, float* __restrict__ C,
    int M, int N, int K)
{
    __shared__ __nv_bfloat16 sA[2][GBM * LDT];
    __shared__ __nv_bfloat16 sB[2][GBN * LDT];

    const int tid  = threadIdx.x;
    const int bm   = blockIdx.y * GBM;
    const int bn   = blockIdx.x * GBN;
    const int warp = tid >> 5;
    const int lane = tid & 31;
    const int wm   = warp & 1;
    const int wn   = warp >> 1;

    wmma::fragment<wmma::accumulator, 16, 16, 16, float> acc[4][2];
    for (int mi = 0; mi < 4; mi++) {
        for (int ni = 0; ni < 2; ni++) {
            wmma::fill_fragment(acc[mi][ni], 0.0f);
        }
    }

    const int r0 = tid >> 2;   // 0..63
    const int c0 = tid & 3;    // 0..3

    const __nv_bfloat16* Aterm[3];
    const __nv_bfloat16* Bterm[3];
    Aterm[0] = Ahi; Bterm[0] = Bhi;
    Aterm[1] = Ahi; Bterm[1] = Blo;
    Aterm[2] = Alo; Bterm[2] = Bhi;

    const int NK  = K / GBK;
    const int TNK = 3 * NK;

    uint4 pa[2];
    uint4 pb[2];

    // load chunk 0 (term 0, k0=0) into registers, store to buffer 0
    for (int j = 0; j < 2; j++) {
        int r = r0 + j * 64;
        pa[j] = *(const uint4*)(Aterm[0] + (size_t)(bm + r) * K + c0 * 8);
        pb[j] = *(const uint4*)(Bterm[0] + (size_t)(bn + r) * K + c0 * 8);
    }
    for (int j = 0; j < 2; j++) {
        int r = r0 + j * 64;
        *(uint4*)&sA[0][r * LDT + c0 * 8] = pa[j];
        *(uint4*)&sB[0][r * LDT + c0 * 8] = pb[j];
    }
    __syncthreads();

    for (int g = 0; g < TNK; g++) {
        const int buf = g & 1;
        if (g + 1 < TNK) {
            const int nt = (g + 1) / NK;
            const int k0 = ((g + 1) - nt * NK) * GBK;
            const __nv_bfloat16* An = Aterm[nt];
            const __nv_bfloat16* Bn = Bterm[nt];
            for (int j = 0; j < 2; j++) {
                int r = r0 + j * 64;
                pa[j] = *(const uint4*)(An + (size_t)(bm + r) * K + k0 + c0 * 8);
                pb[j] = *(const uint4*)(Bn + (size_t)(bn + r) * K + k0 + c0 * 8);
            }
        }

        for (int ks = 0; ks < 2; ks++) {
            wmma::fragment<wmma::matrix_a, 16, 16, 16, __nv_bfloat16, wmma::row_major> afrag[4];
            wmma::fragment<wmma::matrix_b, 16, 16, 16, __nv_bfloat16, wmma::col_major> bfrag[2];
            for (int mi = 0; mi < 4; mi++) {
                wmma::load_matrix_sync(afrag[mi],
                    &sA[buf][(wm * 64 + mi * 16) * LDT + ks * 16], LDT);
            }
            for (int ni = 0; ni < 2; ni++) {
                wmma::load_matrix_sync(bfrag[ni],
                    &sB[buf][(wn * 32 + ni * 16) * LDT + ks * 16], LDT);
            }
            for (int mi = 0; mi < 4; mi++) {
                for (int ni = 0; ni < 2; ni++) {
                    wmma::mma_sync(acc[mi][ni], afrag[mi], bfrag[ni], acc[mi][ni]);
                }
            }
        }
        __syncthreads();

        if (g + 1 < TNK) {
            const int nbuf = buf ^ 1;
            for (int j = 0; j < 2; j++) {
                int r = r0 + j * 64;
                *(uint4*)&sA[nbuf][r * LDT + c0 * 8] = pa[j];
                *(uint4*)&sB[nbuf][r * LDT + c0 * 8] = pb[j];
            }
            __syncthreads();
        }
    }

    // epilogue: per-warp 16x16 patch through smem (reuse sA), add bias, write fp32
    float* patch = (float*)(&sA[0][0]) + warp * 16 * 20;
    const int prow = lane >> 1;
    const int pcol = (lane & 1) * 8;

    for (int mi = 0; mi < 4; mi++) {
        for (int ni = 0; ni < 2; ni++) {
            wmma::store_matrix_sync(patch, acc[mi][ni], 20, wmma::mem_row_major);
            __syncwarp();
            int m = bm + wm * 64 + mi * 16 + prow;
            int n = bn + wn * 32 + ni * 16 + pcol;
            float4 v0 = *(float4*)&patch[prow * 20 + pcol];
            float4 v1 = *(float4*)&patch[prow * 20 + pcol + 4];
            float4 b0 = *(const float4*)&bias[n];
            float4 b1 = *(const float4*)&bias[n + 4];
            v0.x += b0.x; v0.y += b0.y; v0.z += b0.z; v0.w += b0.w;
            v1.x += b1.x; v1.y += b1.y; v1.z += b1.z; v1.w += b1.w;
            *(float4*)&C[(size_t)m * N + n]     = v0;
            *(float4*)&C[(size_t)m * N + n + 4] = v1;
            __syncwarp();
        }
    }
}

// ================= RMSNorm + RoPE (q and k) =================
__global__ void __launch_bounds__(256) norm_rope_kernel(
    float* __restrict__ qbuf, float* __restrict__ kbuf,
    const float* __restrict__ nqw, const float* __restrict__ nkw,
    const float* __restrict__ freqs, const int* __restrict__ grid_sizes)
{
    const int row = blockIdx.x;
    float* buf = blockIdx.y ? kbuf : qbuf;
    const float* w = blockIdx.y ? nkw : nqw;
    const int tid = threadIdx.x;
    float2* rowp = (float2*)(buf + (size_t)row * DIM);
    const float2* wp = (const float2*)w;

    float2 v[3];
    float ss = 0.f;
    for (int i = 0; i < 3; i++) {
        v[i] = rowp[tid + i * 256];
        ss += v[i].x * v[i].x + v[i].y * v[i].y;
    }
    for (int o = 16; o > 0; o >>= 1) {
        ss += __shfl_xor_sync(0xffffffffu, ss, o);
    }
    __shared__ float red[8];
    if ((tid & 31) == 0) {
        red[tid >> 5] = ss;
    }
    __syncthreads();
    float tot = 0.f;
    for (int i = 0; i < 8; i++) {
        tot += red[i];
    }
    const float rms = rsqrtf(tot * (1.0f / DIM) + 1e-6f);

    const int H = grid_sizes[1];
    const int W = grid_sizes[2];
    const int fs = H * W;
    const int fidx = row / fs;
    const int rem = row - fidx * fs;
    const int hh = rem / W;
    const int ww = rem - hh * W;

    for (int i = 0; i < 3; i++) {
        int p = tid + i * 256;
        float2 wv2 = wp[p];
        float a = v[i].x * rms * wv2.x;
        float b = v[i].y * rms * wv2.y;
        int jj = p & 63;
        int frow = (jj < 22) ? fidx : (jj < 43 ? hh : ww);
        float fre = freqs[frow * 128 + jj * 2];
        float fim = freqs[frow * 128 + jj * 2 + 1];
        float2 o;
        o.x = a * fre - b * fim;
        o.y = a * fim + b * fre;
        rowp[p] = o;
    }
}

// ================= Flash attention (fp32) =================
#define BQ 16
#define TK 32
#define KROW 132
#define VROW 160
#define PROW 40

__global__ void __launch_bounds__(128) attn_kernel(
    const float* __restrict__ Q, const float* __restrict__ Kb,
    const float* __restrict__ Vb, float* __restrict__ O,
    const int* __restrict__ grid_sizes)
{
    __shared__ float qs[BQ * 128];
    __shared__ float ks[TK * KROW];
    __shared__ float vs[TK * VROW];
    __shared__ float ps[BQ * PROW];

    const int tid = threadIdx.x;
    const int h = blockIdx.y;
    const int q0 = blockIdx.x * BQ;
    const int H = grid_sizes[1];
    const int W = grid_sizes[2];
    const int fs = H * W;
    const int f = q0 / fs;
    const int kend = (f + 1) * fs;
    const int sink = fs;
    const int wstart = kend - MAX_ATTN;
    const float scale = rsqrtf((float)HD);

    for (int i = 0; i < 4; i++) {
        int idx = tid + i * 128;
        int r = idx >> 5;
        int d4 = idx & 31;
        float4 qv = *(const float4*)&Q[(size_t)(q0 + r) * DIM + h * HD + d4 * 4];
        qv.x *= scale; qv.y *= scale; qv.z *= scale; qv.w *= scale;
        *(float4*)&qs[r * 128 + d4 * 4] = qv;
    }

    const int qi = tid >> 3;
    const int kg = tid & 7;
    const int vposbase = kg * 20;

    float m_i = -1e30f;
    float l_i = 0.f;
    float o[16];
    for (int i = 0; i < 16; i++) {
        o[i] = 0.f;
    }

    for (int k0 = 0; k0 < kend; k0 += TK) {
        if (k0 >= sink && k0 < wstart) {
            continue;
        }
        __syncthreads();
        for (int i = 0; i < 8; i++) {
            int idx = tid + i * 128;
            int kk = idx >> 5;
            int d4 = idx & 31;
            float4 kv = *(const float4*)&Kb[(size_t)(k0 + kk) * DIM + h * HD + d4 * 4];
            *(float4*)&ks[kk * KROW + d4 * 4] = kv;
            float4 vv = *(const float4*)&Vb[(size_t)(k0 + kk) * DIM + h * HD + d4 * 4];
            int pos = d4 * 4 + (d4 >> 2) * 4;
            *(float4*)&vs[kk * VROW + pos] = vv;
        }
        __syncthreads();

        float s0 = 0.f;
        float s1 = 0.f;
        float s2 = 0.f;
        float s3 = 0.f;
        {
            const float4* q4 = (const float4*)&qs[qi * 128];
            for (int d4 = 0; d4 < 32; d4++) {
                float4 qv = q4[d4];
                float4 k0v = *(const float4*)&ks[(kg +  0) * KROW + d4 * 4];
                float4 k1v = *(const float4*)&ks[(kg +  8) * KROW + d4 * 4];
                float4 k2v = *(const float4*)&ks[(kg + 16) * KROW + d4 * 4];
                float4 k3v = *(const float4*)&ks[(kg + 24) * KROW + d4 * 4];
                s0 += qv.x * k0v.x + qv.y * k0v.y + qv.z * k0v.z + qv.w * k0v.w;
                s1 += qv.x * k1v.x + qv.y * k1v.y + qv.z * k1v.z + qv.w * k1v.w;
                s2 += qv.x * k2v.x + qv.y * k2v.y + qv.z * k2v.z + qv.w * k2v.w;
                s3 += qv.x * k3v.x + qv.y * k3v.y + qv.z * k3v.z + qv.w * k3v.w;
            }
        }
        float mt = fmaxf(fmaxf(s0, s1), fmaxf(s2, s3));
        for (int off = 4; off > 0; off >>= 1) {
            mt = fmaxf(mt, __shfl_xor_sync(0xffffffffu, mt, off));
        }
        float m_new = fmaxf(m_i, mt);
        float p0 = __expf(s0 - m_new);
        float p1 = __expf(s1 - m_new);
        float p2 = __expf(s2 - m_new);
        float p3 = __expf(s3 - m_new);
        float psum = p0 + p1 + p2 + p3;
        for (int off = 4; off > 0; off >>= 1) {
            psum += __shfl_xor_sync(0xffffffffu, psum, off);
        }
        float corr = __expf(m_i - m_new);
        l_i = l_i * corr + psum;
        m_i = m_new;
        for (int i = 0; i < 16; i++) {
            o[i] *= corr;
        }
        ps[qi * PROW + kg +  0] = p0;
        ps[qi * PROW + kg +  8] = p1;
        ps[qi * PROW + kg + 16] = p2;
        ps[qi * PROW + kg + 24] = p3;
        __syncwarp();

        for (int kk = 0; kk < TK; kk++) {
            float pv = ps[qi * PROW + kk];
            const float* vrow = &vs[kk * VROW + vposbase];
            for (int t = 0; t < 4; t++) {
                float4 vv = *(const float4*)(vrow + 4 * t);
                o[4 * t + 0] += pv * vv.x;
                o[4 * t + 1] += pv * vv.y;
                o[4 * t + 2] += pv * vv.z;
                o[4 * t + 3] += pv * vv.w;
            }
        }
    }

    const float inv = 1.0f / l_i;
    const int dbase = kg * 16;
    for (int t = 0; t < 4; t++) {
        float4 ov;
        ov.x = o[4 * t + 0] * inv;
        ov.y = o[4 * t + 1] * inv;
        ov.z = o[4 * t + 2] * inv;
        ov.w = o[4 * t + 3] * inv;
        *(float4*)&O[(size_t)(q0 + qi) * DIM + h * HD + dbase + 4 * t] = ov;
    }
}

// ================= launch =================
extern "C" void kernel_launch(void* const* d_in, const int* in_sizes, int n_in,
                              void* d_out, int out_size)
{
    const float* x          = (const float*)d_in[0];
    const int*   grid_sizes = (const int*)  d_in[2];
    const float* freqs      = (const float*)d_in[3];
    const float* wq  = (const float*)d_in[4];
    const float* bq  = (const float*)d_in[5];
    const float* wk  = (const float*)d_in[6];
    const float* bk  = (const float*)d_in[7];
    const float* wv  = (const float*)d_in[8];
    const float* bv  = (const float*)d_in[9];
    const float* wo  = (const float*)d_in[10];
    const float* bo  = (const float*)d_in[11];
    const float* nqw = (const float*)d_in[12];
    const float* nkw = (const float*)d_in[13];

    const int L = in_sizes[0] / DIM;

    float* gq;
    float* gk;
    float* gv;
    float* gao;
    __nv_bfloat16* xhi;
    __nv_bfloat16* xlo;
    __nv_bfloat16* aohi;
    __nv_bfloat16* aolo;
    __nv_bfloat16* whi;
    __nv_bfloat16* wlo;
    cudaGetSymbolAddress((void**)&gq,   g_q);
    cudaGetSymbolAddress((void**)&gk,   g_k);
    cudaGetSymbolAddress((void**)&gv,   g_v);
    cudaGetSymbolAddress((void**)&gao,  g_ao);
    cudaGetSymbolAddress((void**)&xhi,  g_x_hi);
    cudaGetSymbolAddress((void**)&xlo,  g_x_lo);
    cudaGetSymbolAddress((void**)&aohi, g_ao_hi);
    cudaGetSymbolAddress((void**)&aolo, g_ao_lo);
    cudaGetSymbolAddress((void**)&whi,  g_w_hi);
    cudaGetSymbolAddress((void**)&wlo,  g_w_lo);

    const int xN4 = L * DIM / 4;
    const int wN4 = DIM * DIM / 4;
    const size_t WS = (size_t)DIM * DIM;

    f2bf_split_kernel<<<(xN4 + 255) / 256, 256>>>(x,  xhi, xlo, xN4);
    f2bf_split_kernel<<<(wN4 + 255) / 256, 256>>>(wq, whi,          wlo,          wN4);
    f2bf_split_kernel<<<(wN4 + 255) / 256, 256>>>(wk, whi + WS,     wlo + WS,     wN4);
    f2bf_split_kernel<<<(wN4 + 255) / 256, 256>>>(wv, whi + 2 * WS, wlo + 2 * WS, wN4);
    f2bf_split_kernel<<<(wN4 + 255) / 256, 256>>>(wo, whi + 3 * WS, wlo + 3 * WS, wN4);

    dim3 ggrid(DIM / GBN, L / GBM);
    gemm_bf16x3_nt<<<ggrid, 256>>>(xhi, xlo, whi,          wlo,          bq, gq, L, DIM, DIM);
    gemm_bf16x3_nt<<<ggrid, 256>>>(xhi, xlo, whi + WS,     wlo + WS,     bk, gk, L, DIM, DIM);
    gemm_bf16x3_nt<<<ggrid, 256>>>(xhi, xlo, whi + 2 * WS, wlo + 2 * WS, bv, gv, L, DIM, DIM);

    norm_rope_kernel<<<dim3(L, 2), 256>>>(gq, gk, nqw, nkw, freqs, grid_sizes);

    attn_kernel<<<dim3(L / BQ, HEADS), 128>>>(gq, gk, gv, gao, grid_sizes);

    f2bf_split_kernel<<<(xN4 + 255) / 256, 256>>>(gao, aohi, aolo, xN4);
    gemm_bf16x3_nt<<<ggrid, 256>>>(aohi, aolo, whi + 3 * WS, wlo + 3 * WS, bo, (float*)d_out, L, DIM, DIM);
}